// round 1
// baseline (speedup 1.0000x reference)
#include <cuda_runtime.h>
#include <cuda_bf16.h>
#include <math.h>

// ---------------------------------------------------------------------------
// NonstationaryGaussianSpectralMixtureKernel
//   K[i,j] = sum_q wX wY * sqrt(2 sX sY)/(sX^2+sY^2) * exp(-d2/(sX^2+sY^2))
//                 * cos(2pi(phY-phX))
// Phase 1: per-point features  u = A*cos(2pi ph), v = A*sin(2pi ph), s2 = s^2
//          with A = w*sqrt(s)*2^(1/4).  Then
//   K[i,j] = sum_q (uX uY + vX vY) * r * exp2(-d2*log2e*r),  r = 1/(s2X+s2Y)
// => 2 MUFU (rcp.approx, ex2.approx) + ~6 FMA per (pair,q).
// ---------------------------------------------------------------------------

#define MAXPTS 8192
// [side][row][point];  row = q (u), 8+q (v), 16+q (s2)
__device__ float g_feat[2][24][MAXPTS];

__device__ __forceinline__ float frcp_fast(float x) {
    float r; asm("rcp.approx.f32 %0, %1;" : "=f"(r) : "f"(x)); return r;
}
__device__ __forceinline__ float fex2_fast(float x) {
    float r; asm("ex2.approx.f32 %0, %1;" : "=f"(r) : "f"(x)); return r;
}

__device__ __forceinline__ float selu_f(float x) {
    const float scale = 1.0507009873554805f;
    const float alpha = 1.6732632423543772f;
    return (x > 0.0f) ? scale * x : scale * alpha * expm1f(x);
}
__device__ __forceinline__ float softplus_f(float x) {
    // log(1+exp(x)) = max(x,0) + log1p(exp(-|x|))
    return fmaxf(x, 0.0f) + log1pf(expf(-fabsf(x)));
}

// ---------------------------------------------------------------------------
// Phase 1: per-point feature kernel. One thread per point (x then y).
// ---------------------------------------------------------------------------
__global__ void feat_kernel(
    const float* __restrict__ x, const float* __restrict__ y,
    const float* __restrict__ W1, const float* __restrict__ b1,
    const float* __restrict__ Ww, const float* __restrict__ bw,
    const float* __restrict__ Wf, const float* __restrict__ bf,
    const float* __restrict__ Ws, const float* __restrict__ bs,
    int N, int M)
{
    __shared__ float sW1[64 * 3];
    __shared__ float sb1[64];
    __shared__ float sWw[8 * 64];
    __shared__ float sbw[8];
    __shared__ float sWf[24 * 64];
    __shared__ float sbf[24];
    __shared__ float sWs[8 * 64];
    __shared__ float sbs[8];

    int tid = threadIdx.x;
    for (int i = tid; i < 64 * 3; i += blockDim.x) sW1[i] = W1[i];
    for (int i = tid; i < 64;     i += blockDim.x) sb1[i] = b1[i];
    for (int i = tid; i < 8 * 64; i += blockDim.x) sWw[i] = Ww[i];
    for (int i = tid; i < 8;      i += blockDim.x) sbw[i] = bw[i];
    for (int i = tid; i < 24 * 64;i += blockDim.x) sWf[i] = Wf[i];
    for (int i = tid; i < 24;     i += blockDim.x) sbf[i] = bf[i];
    for (int i = tid; i < 8 * 64; i += blockDim.x) sWs[i] = Ws[i];
    for (int i = tid; i < 8;      i += blockDim.x) sbs[i] = bs[i];
    __syncthreads();

    int p = blockIdx.x * blockDim.x + tid;
    int total = N + M;
    if (p >= total) return;

    int side = (p < N) ? 0 : 1;
    int pt   = (p < N) ? p : p - N;
    const float* P = (p < N) ? (x + 3 * p) : (y + 3 * (p - N));
    float P0 = P[0], P1 = P[1], P2 = P[2];

    float h[64];
#pragma unroll
    for (int l = 0; l < 64; l++) {
        float t = sb1[l];
        t = fmaf(sW1[l * 3 + 0], P0, t);
        t = fmaf(sW1[l * 3 + 1], P1, t);
        t = fmaf(sW1[l * 3 + 2], P2, t);
        h[l] = selu_f(t);
    }

    const float TWO_PI  = 6.283185307179586f;
    const float ROOT4_2 = 1.1892071150027210f;  // 2^(1/4)

#pragma unroll
    for (int q = 0; q < 8; q++) {
        float aw = sbw[q], as = sbs[q];
        float f0 = sbf[q * 3 + 0], f1 = sbf[q * 3 + 1], f2 = sbf[q * 3 + 2];
#pragma unroll
        for (int l = 0; l < 64; l++) {
            float hl = h[l];
            aw = fmaf(sWw[q * 64 + l], hl, aw);
            as = fmaf(sWs[q * 64 + l], hl, as);
            f0 = fmaf(sWf[(q * 3 + 0) * 64 + l], hl, f0);
            f1 = fmaf(sWf[(q * 3 + 1) * 64 + l], hl, f1);
            f2 = fmaf(sWf[(q * 3 + 2) * 64 + l], hl, f2);
        }
        float w = softplus_f(aw);
        float s = softplus_f(as);
        float g0 = softplus_f(f0);
        float g1 = softplus_f(f1);
        float g2 = softplus_f(f2);
        float phase = g0 * P0 + g1 * P1 + g2 * P2;
        float ang = TWO_PI * phase;
        float sv, cv;
        sincosf(ang, &sv, &cv);
        float A = w * sqrtf(s) * ROOT4_2;

        g_feat[side][q][pt]      = A * cv;   // u
        g_feat[side][8 + q][pt]  = A * sv;   // v
        g_feat[side][16 + q][pt] = s * s;    // s2
    }
}

// ---------------------------------------------------------------------------
// Phase 2: pair kernel. 64x64 tile per 256-thread block, 4x4 micro-tile.
// ---------------------------------------------------------------------------
__global__ void __launch_bounds__(256)
pair_kernel(const float* __restrict__ x, const float* __restrict__ y,
            float* __restrict__ out, int N, int M)
{
    __shared__ float sfx[24][64];   // x features [row][i_local]
    __shared__ float sfy[24][64];   // y features [row][j_local]
    __shared__ float spx[3][64];    // x coords
    __shared__ float spy[3][64];    // y coords

    int tid = threadIdx.x;
    int i0 = blockIdx.y * 64;
    int j0 = blockIdx.x * 64;

    // Load features (pad: u=v=0, s2=1 -> zero contribution, no NaN)
    for (int idx = tid; idx < 24 * 64; idx += 256) {
        int r = idx >> 6, c = idx & 63;
        float pad = (r >= 16) ? 1.0f : 0.0f;
        int gi = i0 + c;
        sfx[r][c] = (gi < N) ? g_feat[0][r][gi] : pad;
        int gj = j0 + c;
        sfy[r][c] = (gj < M) ? g_feat[1][r][gj] : pad;
    }
    for (int idx = tid; idx < 3 * 64; idx += 256) {
        int d = idx >> 6, c = idx & 63;
        int gi = i0 + c;
        spx[d][c] = (gi < N) ? x[gi * 3 + d] : 0.0f;
        int gj = j0 + c;
        spy[d][c] = (gj < M) ? y[gj * 3 + d] : 0.0f;
    }
    __syncthreads();

    int tx = tid & 15;      // j group
    int ty = tid >> 4;      // i group
    int ib = ty * 4;
    int jb = tx * 4;

    const float LOG2E = 1.4426950408889634f;

    // d2 * log2e for the 4x4 micro-tile
    float4 px0 = *(const float4*)&spx[0][ib];
    float4 px1 = *(const float4*)&spx[1][ib];
    float4 px2 = *(const float4*)&spx[2][ib];
    float4 py0 = *(const float4*)&spy[0][jb];
    float4 py1 = *(const float4*)&spy[1][jb];
    float4 py2 = *(const float4*)&spy[2][jb];

    float xa0[4] = {px0.x, px0.y, px0.z, px0.w};
    float xa1[4] = {px1.x, px1.y, px1.z, px1.w};
    float xa2[4] = {px2.x, px2.y, px2.z, px2.w};
    float ya0[4] = {py0.x, py0.y, py0.z, py0.w};
    float ya1[4] = {py1.x, py1.y, py1.z, py1.w};
    float ya2[4] = {py2.x, py2.y, py2.z, py2.w};

    float d2L[4][4];
#pragma unroll
    for (int ii = 0; ii < 4; ii++) {
#pragma unroll
        for (int jj = 0; jj < 4; jj++) {
            float dx = xa0[ii] - ya0[jj];
            float dy = xa1[ii] - ya1[jj];
            float dz = xa2[ii] - ya2[jj];
            float d2 = fmaf(dx, dx, fmaf(dy, dy, dz * dz));
            d2L[ii][jj] = d2 * LOG2E;
        }
    }

    float acc[4][4];
#pragma unroll
    for (int ii = 0; ii < 4; ii++)
#pragma unroll
        for (int jj = 0; jj < 4; jj++) acc[ii][jj] = 0.0f;

#pragma unroll
    for (int q = 0; q < 8; q++) {
        float4 ux4 = *(const float4*)&sfx[q][ib];
        float4 vx4 = *(const float4*)&sfx[8 + q][ib];
        float4 wx4 = *(const float4*)&sfx[16 + q][ib];
        float4 uy4 = *(const float4*)&sfy[q][jb];
        float4 vy4 = *(const float4*)&sfy[8 + q][jb];
        float4 wy4 = *(const float4*)&sfy[16 + q][jb];

        float ux[4] = {ux4.x, ux4.y, ux4.z, ux4.w};
        float vx[4] = {vx4.x, vx4.y, vx4.z, vx4.w};
        float wx[4] = {wx4.x, wx4.y, wx4.z, wx4.w};
        float uy[4] = {uy4.x, uy4.y, uy4.z, uy4.w};
        float vy[4] = {vy4.x, vy4.y, vy4.z, vy4.w};
        float wy[4] = {wy4.x, wy4.y, wy4.z, wy4.w};

#pragma unroll
        for (int ii = 0; ii < 4; ii++) {
#pragma unroll
            for (int jj = 0; jj < 4; jj++) {
                float s2 = wx[ii] + wy[jj];
                float r  = frcp_fast(s2);
                float e  = fex2_fast(-d2L[ii][jj] * r);
                float cc = fmaf(ux[ii], uy[jj], vx[ii] * vy[jj]);
                acc[ii][jj] = fmaf(cc, r * e, acc[ii][jj]);
            }
        }
    }

    // Store 4x float4 rows, guarded
#pragma unroll
    for (int ii = 0; ii < 4; ii++) {
        int i = i0 + ib + ii;
        if (i >= N) continue;
        int j = j0 + jb;
        if (j + 3 < M) {
            float4 v = make_float4(acc[ii][0], acc[ii][1], acc[ii][2], acc[ii][3]);
            *(float4*)&out[(size_t)i * M + j] = v;
        } else {
#pragma unroll
            for (int jj = 0; jj < 4; jj++)
                if (j + jj < M) out[(size_t)i * M + j + jj] = acc[ii][jj];
        }
    }
}

// ---------------------------------------------------------------------------
extern "C" void kernel_launch(void* const* d_in, const int* in_sizes, int n_in,
                              void* d_out, int out_size) {
    const float* x  = (const float*)d_in[0];
    const float* y  = (const float*)d_in[1];
    const float* W1 = (const float*)d_in[2];
    const float* b1 = (const float*)d_in[3];
    const float* Ww = (const float*)d_in[4];
    const float* bw = (const float*)d_in[5];
    const float* Wf = (const float*)d_in[6];
    const float* bf = (const float*)d_in[7];
    const float* Ws = (const float*)d_in[8];
    const float* bs = (const float*)d_in[9];
    float* out = (float*)d_out;

    int N = in_sizes[0] / 3;
    int M = in_sizes[1] / 3;

    int total = N + M;
    feat_kernel<<<(total + 255) / 256, 256>>>(x, y, W1, b1, Ww, bw, Wf, bf,
                                              Ws, bs, N, M);

    dim3 grid((M + 63) / 64, (N + 63) / 64);
    pair_kernel<<<grid, 256>>>(x, y, out, N, M);
}

// round 2
// speedup vs baseline: 1.7333x; 1.7333x over previous
#include <cuda_runtime.h>
#include <cuda_bf16.h>
#include <math.h>

// ---------------------------------------------------------------------------
// NonstationaryGaussianSpectralMixtureKernel
//   K[i,j] = sum_q wX wY * sqrt(2 sX sY)/(sX^2+sY^2) * exp(-d2/(sX^2+sY^2))
//                 * cos(2pi(phY-phX))
// Phase 1 (per point): u = A*cos(2pi ph), v = A*sin(2pi ph), s2 = s^2,
//   A = w*sqrt(s)*2^(1/4).
// Phase 2: K[i,j] = sum_q (uX uY + vX vY) * r * exp2(d2L * r),
//   r = 1/(s2X+s2Y), d2L = -d2*log2(e).
// rcp via magic+2 Newton (fp pipes), exp2 via MUFU => 1 MUFU per (pair,q).
// ---------------------------------------------------------------------------

#define MAXPTS 8192
// [side][row][point];  row = q (u), 8+q (v), 16+q (s2)
__device__ float g_feat[2][24][MAXPTS];

__device__ __forceinline__ float fex2_fast(float x) {
    float r; asm("ex2.approx.f32 %0, %1;" : "=f"(r) : "f"(x)); return r;
}
// reciprocal on the fma/alu pipes: magic seed + 2 Newton iterations (~6e-6 rel)
__device__ __forceinline__ float frcp_nr(float x) {
    float r = __int_as_float(0x7EF311C3 - __float_as_int(x));
    r = r * (2.0f - x * r);
    r = r * (2.0f - x * r);
    return r;
}

__device__ __forceinline__ float selu_f(float x) {
    const float scale = 1.0507009873554805f;
    const float alpha = 1.6732632423543772f;
    return (x > 0.0f) ? scale * x : scale * alpha * expm1f(x);
}
__device__ __forceinline__ float softplus_f(float x) {
    return fmaxf(x, 0.0f) + log1pf(expf(-fabsf(x)));
}

// ---------------------------------------------------------------------------
// Phase 1 v2: 8 threads per point (one per q), 32 points per 256-thread block.
// Hidden layer h computed cooperatively into shared memory.
// ---------------------------------------------------------------------------
__global__ void __launch_bounds__(256)
feat_kernel(
    const float* __restrict__ x, const float* __restrict__ y,
    const float* __restrict__ W1, const float* __restrict__ b1,
    const float* __restrict__ Ww, const float* __restrict__ bw,
    const float* __restrict__ Wf, const float* __restrict__ bf,
    const float* __restrict__ Ws, const float* __restrict__ bs,
    int N, int M)
{
    __shared__ float sW1[64 * 3];
    __shared__ float sb1[64];
    __shared__ float sHw[64][9];    // transposed Ww: [l][q]
    __shared__ float sHs[64][9];    // transposed Ws: [l][q]
    __shared__ float sHf[64][25];   // transposed Wf: [l][3q+d]
    __shared__ float sbw[8], sbs[8], sbf[24];
    __shared__ float sh_h[32][65];  // hidden activations per local point

    int tid = threadIdx.x;
    for (int i = tid; i < 64 * 3; i += 256) sW1[i] = W1[i];
    for (int i = tid; i < 64;     i += 256) sb1[i] = b1[i];
    for (int i = tid; i < 8 * 64; i += 256) {
        int q = i >> 6, l = i & 63;
        sHw[l][q] = Ww[i];
        sHs[l][q] = Ws[i];
    }
    for (int i = tid; i < 24 * 64; i += 256) {
        int r = i >> 6, l = i & 63;
        sHf[l][r] = Wf[i];
    }
    if (tid < 8)  { sbw[tid] = bw[tid]; sbs[tid] = bs[tid]; }
    if (tid < 24) { sbf[tid] = bf[tid]; }
    __syncthreads();

    int pl    = tid >> 3;   // local point 0..31
    int lane8 = tid & 7;    // sub-lane / q index
    int pg    = blockIdx.x * 32 + pl;
    int total = N + M;

    float P0 = 0.0f, P1 = 0.0f, P2 = 0.0f;
    int side = 0, pt = 0;
    bool valid = (pg < total);
    if (valid) {
        side = (pg < N) ? 0 : 1;
        pt   = (pg < N) ? pg : pg - N;
        const float* P = (pg < N) ? (x + 3 * pg) : (y + 3 * (pg - N));
        P0 = P[0]; P1 = P[1]; P2 = P[2];
    }

    // Step 1: each thread computes 8 hidden units (contiguous chunk)
    {
        int lbase = lane8 * 8;
#pragma unroll
        for (int k = 0; k < 8; k++) {
            int l = lbase + k;
            float t = sb1[l];
            t = fmaf(sW1[l * 3 + 0], P0, t);
            t = fmaf(sW1[l * 3 + 1], P1, t);
            t = fmaf(sW1[l * 3 + 2], P2, t);
            sh_h[pl][l] = selu_f(t);
        }
    }
    __syncthreads();

    if (!valid) return;

    // Step 2: this thread handles q = lane8 for its point
    int q = lane8;
    float aw = sbw[q], as = sbs[q];
    float f0 = sbf[q * 3 + 0], f1 = sbf[q * 3 + 1], f2 = sbf[q * 3 + 2];
#pragma unroll
    for (int l = 0; l < 64; l++) {
        float hl = sh_h[pl][l];
        aw = fmaf(sHw[l][q], hl, aw);
        as = fmaf(sHs[l][q], hl, as);
        f0 = fmaf(sHf[l][q * 3 + 0], hl, f0);
        f1 = fmaf(sHf[l][q * 3 + 1], hl, f1);
        f2 = fmaf(sHf[l][q * 3 + 2], hl, f2);
    }

    float w  = softplus_f(aw);
    float s  = softplus_f(as);
    float g0 = softplus_f(f0);
    float g1 = softplus_f(f1);
    float g2 = softplus_f(f2);
    float phase = g0 * P0 + g1 * P1 + g2 * P2;

    const float TWO_PI  = 6.283185307179586f;
    const float ROOT4_2 = 1.1892071150027210f;  // 2^(1/4)
    float sv, cv;
    sincosf(TWO_PI * phase, &sv, &cv);
    float A = w * sqrtf(s) * ROOT4_2;

    g_feat[side][q][pt]      = A * cv;   // u
    g_feat[side][8 + q][pt]  = A * sv;   // v
    g_feat[side][16 + q][pt] = s * s;    // s2
}

// ---------------------------------------------------------------------------
// Phase 2: pair kernel. 64x64 tile per 256-thread block, 4x4 micro-tile.
// ---------------------------------------------------------------------------
__global__ void __launch_bounds__(256)
pair_kernel(const float* __restrict__ x, const float* __restrict__ y,
            float* __restrict__ out, int N, int M)
{
    __shared__ float sfx[24][64];   // x features [row][i_local]
    __shared__ float sfy[24][64];   // y features [row][j_local]
    __shared__ float spx[3][64];    // x coords
    __shared__ float spy[3][64];    // y coords

    int tid = threadIdx.x;
    int i0 = blockIdx.y * 64;
    int j0 = blockIdx.x * 64;

    // Load features (pad: u=v=0, s2=1 -> zero contribution, no NaN)
    for (int idx = tid; idx < 24 * 64; idx += 256) {
        int r = idx >> 6, c = idx & 63;
        float pad = (r >= 16) ? 1.0f : 0.0f;
        int gi = i0 + c;
        sfx[r][c] = (gi < N) ? g_feat[0][r][gi] : pad;
        int gj = j0 + c;
        sfy[r][c] = (gj < M) ? g_feat[1][r][gj] : pad;
    }
    for (int idx = tid; idx < 3 * 64; idx += 256) {
        int d = idx >> 6, c = idx & 63;
        int gi = i0 + c;
        spx[d][c] = (gi < N) ? x[gi * 3 + d] : 0.0f;
        int gj = j0 + c;
        spy[d][c] = (gj < M) ? y[gj * 3 + d] : 0.0f;
    }
    __syncthreads();

    int tx = tid & 15;      // j group
    int ty = tid >> 4;      // i group
    int ib = ty * 4;
    int jb = tx * 4;

    const float NLOG2E = -1.4426950408889634f;

    float4 px0 = *(const float4*)&spx[0][ib];
    float4 px1 = *(const float4*)&spx[1][ib];
    float4 px2 = *(const float4*)&spx[2][ib];
    float4 py0 = *(const float4*)&spy[0][jb];
    float4 py1 = *(const float4*)&spy[1][jb];
    float4 py2 = *(const float4*)&spy[2][jb];

    float xa0[4] = {px0.x, px0.y, px0.z, px0.w};
    float xa1[4] = {px1.x, px1.y, px1.z, px1.w};
    float xa2[4] = {px2.x, px2.y, px2.z, px2.w};
    float ya0[4] = {py0.x, py0.y, py0.z, py0.w};
    float ya1[4] = {py1.x, py1.y, py1.z, py1.w};
    float ya2[4] = {py2.x, py2.y, py2.z, py2.w};

    // d2L = -d2*log2e for the 4x4 micro-tile (negation folded here)
    float d2L[4][4];
#pragma unroll
    for (int ii = 0; ii < 4; ii++) {
#pragma unroll
        for (int jj = 0; jj < 4; jj++) {
            float dx = xa0[ii] - ya0[jj];
            float dy = xa1[ii] - ya1[jj];
            float dz = xa2[ii] - ya2[jj];
            float d2 = fmaf(dx, dx, fmaf(dy, dy, dz * dz));
            d2L[ii][jj] = d2 * NLOG2E;
        }
    }

    float acc[4][4];
#pragma unroll
    for (int ii = 0; ii < 4; ii++)
#pragma unroll
        for (int jj = 0; jj < 4; jj++) acc[ii][jj] = 0.0f;

#pragma unroll
    for (int q = 0; q < 8; q++) {
        float4 ux4 = *(const float4*)&sfx[q][ib];
        float4 vx4 = *(const float4*)&sfx[8 + q][ib];
        float4 wx4 = *(const float4*)&sfx[16 + q][ib];
        float4 uy4 = *(const float4*)&sfy[q][jb];
        float4 vy4 = *(const float4*)&sfy[8 + q][jb];
        float4 wy4 = *(const float4*)&sfy[16 + q][jb];

        float ux[4] = {ux4.x, ux4.y, ux4.z, ux4.w};
        float vx[4] = {vx4.x, vx4.y, vx4.z, vx4.w};
        float wx[4] = {wx4.x, wx4.y, wx4.z, wx4.w};
        float uy[4] = {uy4.x, uy4.y, uy4.z, uy4.w};
        float vy[4] = {vy4.x, vy4.y, vy4.z, vy4.w};
        float wy[4] = {wy4.x, wy4.y, wy4.z, wy4.w};

#pragma unroll
        for (int ii = 0; ii < 4; ii++) {
#pragma unroll
            for (int jj = 0; jj < 4; jj++) {
                float s2 = wx[ii] + wy[jj];
                float r  = frcp_nr(s2);              // fp pipes, no MUFU
                float e  = fex2_fast(d2L[ii][jj] * r); // 1 MUFU
                float cc = fmaf(ux[ii], uy[jj], vx[ii] * vy[jj]);
                acc[ii][jj] = fmaf(cc, r * e, acc[ii][jj]);
            }
        }
    }

    // Store 4x float4 rows, guarded
#pragma unroll
    for (int ii = 0; ii < 4; ii++) {
        int i = i0 + ib + ii;
        if (i >= N) continue;
        int j = j0 + jb;
        if (j + 3 < M) {
            float4 v = make_float4(acc[ii][0], acc[ii][1], acc[ii][2], acc[ii][3]);
            *(float4*)&out[(size_t)i * M + j] = v;
        } else {
#pragma unroll
            for (int jj = 0; jj < 4; jj++)
                if (j + jj < M) out[(size_t)i * M + j + jj] = acc[ii][jj];
        }
    }
}

// ---------------------------------------------------------------------------
extern "C" void kernel_launch(void* const* d_in, const int* in_sizes, int n_in,
                              void* d_out, int out_size) {
    const float* x  = (const float*)d_in[0];
    const float* y  = (const float*)d_in[1];
    const float* W1 = (const float*)d_in[2];
    const float* b1 = (const float*)d_in[3];
    const float* Ww = (const float*)d_in[4];
    const float* bw = (const float*)d_in[5];
    const float* Wf = (const float*)d_in[6];
    const float* bf = (const float*)d_in[7];
    const float* Ws = (const float*)d_in[8];
    const float* bs = (const float*)d_in[9];
    float* out = (float*)d_out;

    int N = in_sizes[0] / 3;
    int M = in_sizes[1] / 3;

    int total = N + M;
    feat_kernel<<<(total + 31) / 32, 256>>>(x, y, W1, b1, Ww, bw, Wf, bf,
                                            Ws, bs, N, M);

    dim3 grid((M + 63) / 64, (N + 63) / 64);
    pair_kernel<<<grid, 256>>>(x, y, out, N, M);
}

// round 3
// speedup vs baseline: 1.7502x; 1.0098x over previous
#include <cuda_runtime.h>
#include <cuda_bf16.h>
#include <math.h>

// ---------------------------------------------------------------------------
// NonstationaryGaussianSpectralMixtureKernel
// Phase 1 (per point): u = A*cos(2pi ph), v = A*sin(2pi ph), s2 = s^2,
//   A = w*sqrt(s)*2^(1/4).
// Phase 2: K[i,j] = sum_q (uX uY + vX vY) * r * exp2(d2L * r),
//   r = 1/(s2X+s2Y), d2L = -d2*log2(e).
// Inner loop packed 2-wide in j with Blackwell f32x2 ops:
//   5 fma-pipe slots + 1 MUFU + ~2.5 alu per (pair,q).
// ---------------------------------------------------------------------------

#define MAXPTS 8192
// [side][row][point];  row = q (u), 8+q (v), 16+q (s2)
__device__ float g_feat[2][24][MAXPTS];

typedef unsigned long long u64;

__device__ __forceinline__ float fex2_fast(float x) {
    float r; asm("ex2.approx.f32 %0, %1;" : "=f"(r) : "f"(x)); return r;
}
__device__ __forceinline__ u64 pack2(float lo, float hi) {
    u64 r; asm("mov.b64 %0, {%1, %2};" : "=l"(r) : "f"(lo), "f"(hi)); return r;
}
__device__ __forceinline__ void unpack2(u64 p, float& lo, float& hi) {
    asm("mov.b64 {%0, %1}, %2;" : "=f"(lo), "=f"(hi) : "l"(p));
}
__device__ __forceinline__ u64 fma2(u64 a, u64 b, u64 c) {
    u64 r; asm("fma.rn.f32x2 %0, %1, %2, %3;" : "=l"(r) : "l"(a), "l"(b), "l"(c));
    return r;
}
__device__ __forceinline__ u64 mul2(u64 a, u64 b) {
    u64 r; asm("mul.rn.f32x2 %0, %1, %2;" : "=l"(r) : "l"(a), "l"(b)); return r;
}
__device__ __forceinline__ u64 add2(u64 a, u64 b) {
    u64 r; asm("add.rn.f32x2 %0, %1, %2;" : "=l"(r) : "l"(a), "l"(b)); return r;
}

// Packed reciprocal: magic seed (single 64-bit int sub; per-half exact since
// s2's float bits < 0x7EF311C3 for all physical s2, so no cross-half borrow)
// + 2 packed Newton iterations. ~1.4e-6 rel err.
__device__ __forceinline__ u64 rcp2_nr(u64 x) {
    const u64 MAGIC2 = 0x7EF311C37EF311C3ULL;
    const u64 SIGN2  = 0x8000000080000000ULL;
    const u64 TWO2   = 0x4000000040000000ULL;  // {2.0f, 2.0f}
    u64 r  = MAGIC2 - x;
    u64 nx = x ^ SIGN2;
    r = mul2(r, fma2(nx, r, TWO2));
    r = mul2(r, fma2(nx, r, TWO2));
    return r;
}

__device__ __forceinline__ float selu_f(float x) {
    const float scale = 1.0507009873554805f;
    const float alpha = 1.6732632423543772f;
    return (x > 0.0f) ? scale * x : scale * alpha * expm1f(x);
}
__device__ __forceinline__ float softplus_f(float x) {
    return fmaxf(x, 0.0f) + log1pf(expf(-fabsf(x)));
}

// ---------------------------------------------------------------------------
// Phase 1: 8 threads per point (one per q), 32 points per 256-thread block.
// ---------------------------------------------------------------------------
__global__ void __launch_bounds__(256)
feat_kernel(
    const float* __restrict__ x, const float* __restrict__ y,
    const float* __restrict__ W1, const float* __restrict__ b1,
    const float* __restrict__ Ww, const float* __restrict__ bw,
    const float* __restrict__ Wf, const float* __restrict__ bf,
    const float* __restrict__ Ws, const float* __restrict__ bs,
    int N, int M)
{
    __shared__ float sW1[64 * 3];
    __shared__ float sb1[64];
    __shared__ float sHw[64][9];    // transposed Ww: [l][q]
    __shared__ float sHs[64][9];    // transposed Ws: [l][q]
    __shared__ float sHf[64][25];   // transposed Wf: [l][3q+d]
    __shared__ float sbw[8], sbs[8], sbf[24];
    __shared__ float sh_h[32][65];  // hidden activations per local point

    int tid = threadIdx.x;
    for (int i = tid; i < 64 * 3; i += 256) sW1[i] = W1[i];
    for (int i = tid; i < 64;     i += 256) sb1[i] = b1[i];
    for (int i = tid; i < 8 * 64; i += 256) {
        int q = i >> 6, l = i & 63;
        sHw[l][q] = Ww[i];
        sHs[l][q] = Ws[i];
    }
    for (int i = tid; i < 24 * 64; i += 256) {
        int r = i >> 6, l = i & 63;
        sHf[l][r] = Wf[i];
    }
    if (tid < 8)  { sbw[tid] = bw[tid]; sbs[tid] = bs[tid]; }
    if (tid < 24) { sbf[tid] = bf[tid]; }
    __syncthreads();

    int pl    = tid >> 3;   // local point 0..31
    int lane8 = tid & 7;    // q index
    int pg    = blockIdx.x * 32 + pl;
    int total = N + M;

    float P0 = 0.0f, P1 = 0.0f, P2 = 0.0f;
    int side = 0, pt = 0;
    bool valid = (pg < total);
    if (valid) {
        side = (pg < N) ? 0 : 1;
        pt   = (pg < N) ? pg : pg - N;
        const float* P = (pg < N) ? (x + 3 * pg) : (y + 3 * (pg - N));
        P0 = P[0]; P1 = P[1]; P2 = P[2];
    }

    {
        int lbase = lane8 * 8;
#pragma unroll
        for (int k = 0; k < 8; k++) {
            int l = lbase + k;
            float t = sb1[l];
            t = fmaf(sW1[l * 3 + 0], P0, t);
            t = fmaf(sW1[l * 3 + 1], P1, t);
            t = fmaf(sW1[l * 3 + 2], P2, t);
            sh_h[pl][l] = selu_f(t);
        }
    }
    __syncthreads();

    if (!valid) return;

    int q = lane8;
    float aw = sbw[q], as = sbs[q];
    float f0 = sbf[q * 3 + 0], f1 = sbf[q * 3 + 1], f2 = sbf[q * 3 + 2];
#pragma unroll
    for (int l = 0; l < 64; l++) {
        float hl = sh_h[pl][l];
        aw = fmaf(sHw[l][q], hl, aw);
        as = fmaf(sHs[l][q], hl, as);
        f0 = fmaf(sHf[l][q * 3 + 0], hl, f0);
        f1 = fmaf(sHf[l][q * 3 + 1], hl, f1);
        f2 = fmaf(sHf[l][q * 3 + 2], hl, f2);
    }

    float w  = softplus_f(aw);
    float s  = softplus_f(as);
    float g0 = softplus_f(f0);
    float g1 = softplus_f(f1);
    float g2 = softplus_f(f2);
    float phase = g0 * P0 + g1 * P1 + g2 * P2;

    const float TWO_PI  = 6.283185307179586f;
    const float ROOT4_2 = 1.1892071150027210f;  // 2^(1/4)
    float sv, cv;
    sincosf(TWO_PI * phase, &sv, &cv);
    float A = w * sqrtf(s) * ROOT4_2;

    g_feat[side][q][pt]      = A * cv;   // u
    g_feat[side][8 + q][pt]  = A * sv;   // v
    g_feat[side][16 + q][pt] = s * s;    // s2
}

// ---------------------------------------------------------------------------
// Phase 2: pair kernel. 64x64 tile per 256-thread block, 4x4 micro-tile,
// inner loop packed 2-wide in j via f32x2.
// ---------------------------------------------------------------------------
__global__ void __launch_bounds__(256)
pair_kernel(const float* __restrict__ x, const float* __restrict__ y,
            float* __restrict__ out, int N, int M)
{
    __shared__ float sfx[24][64];
    __shared__ float sfy[24][64];
    __shared__ float spx[3][64];
    __shared__ float spy[3][64];

    int tid = threadIdx.x;
    int i0 = blockIdx.y * 64;
    int j0 = blockIdx.x * 64;

    for (int idx = tid; idx < 24 * 64; idx += 256) {
        int r = idx >> 6, c = idx & 63;
        float pad = (r >= 16) ? 1.0f : 0.0f;
        int gi = i0 + c;
        sfx[r][c] = (gi < N) ? g_feat[0][r][gi] : pad;
        int gj = j0 + c;
        sfy[r][c] = (gj < M) ? g_feat[1][r][gj] : pad;
    }
    for (int idx = tid; idx < 3 * 64; idx += 256) {
        int d = idx >> 6, c = idx & 63;
        int gi = i0 + c;
        spx[d][c] = (gi < N) ? x[gi * 3 + d] : 0.0f;
        int gj = j0 + c;
        spy[d][c] = (gj < M) ? y[gj * 3 + d] : 0.0f;
    }
    __syncthreads();

    int tx = tid & 15;      // j group
    int ty = tid >> 4;      // i group
    int ib = ty * 4;
    int jb = tx * 4;

    const float NLOG2E = -1.4426950408889634f;

    float4 px0 = *(const float4*)&spx[0][ib];
    float4 px1 = *(const float4*)&spx[1][ib];
    float4 px2 = *(const float4*)&spx[2][ib];
    float4 py0 = *(const float4*)&spy[0][jb];
    float4 py1 = *(const float4*)&spy[1][jb];
    float4 py2 = *(const float4*)&spy[2][jb];

    float xa0[4] = {px0.x, px0.y, px0.z, px0.w};
    float xa1[4] = {px1.x, px1.y, px1.z, px1.w};
    float xa2[4] = {px2.x, px2.y, px2.z, px2.w};
    float ya0[4] = {py0.x, py0.y, py0.z, py0.w};
    float ya1[4] = {py1.x, py1.y, py1.z, py1.w};
    float ya2[4] = {py2.x, py2.y, py2.z, py2.w};

    // d2L = -d2*log2e, packed over j pairs: d2Lp[ii][jp] = {jj=2jp, jj=2jp+1}
    u64 d2Lp[4][2];
#pragma unroll
    for (int ii = 0; ii < 4; ii++) {
        float t[4];
#pragma unroll
        for (int jj = 0; jj < 4; jj++) {
            float dx = xa0[ii] - ya0[jj];
            float dy = xa1[ii] - ya1[jj];
            float dz = xa2[ii] - ya2[jj];
            float d2 = fmaf(dx, dx, fmaf(dy, dy, dz * dz));
            t[jj] = d2 * NLOG2E;
        }
        d2Lp[ii][0] = pack2(t[0], t[1]);
        d2Lp[ii][1] = pack2(t[2], t[3]);
    }

    u64 acc[4][2];
#pragma unroll
    for (int ii = 0; ii < 4; ii++) {
        acc[ii][0] = 0ULL;
        acc[ii][1] = 0ULL;
    }

#pragma unroll
    for (int q = 0; q < 8; q++) {
        float4 ux4 = *(const float4*)&sfx[q][ib];
        float4 vx4 = *(const float4*)&sfx[8 + q][ib];
        float4 wx4 = *(const float4*)&sfx[16 + q][ib];
        float4 uy4 = *(const float4*)&sfy[q][jb];
        float4 vy4 = *(const float4*)&sfy[8 + q][jb];
        float4 wy4 = *(const float4*)&sfy[16 + q][jb];

        u64 uyp[2] = {pack2(uy4.x, uy4.y), pack2(uy4.z, uy4.w)};
        u64 vyp[2] = {pack2(vy4.x, vy4.y), pack2(vy4.z, vy4.w)};
        u64 wyp[2] = {pack2(wy4.x, wy4.y), pack2(wy4.z, wy4.w)};

        float ux[4] = {ux4.x, ux4.y, ux4.z, ux4.w};
        float vx[4] = {vx4.x, vx4.y, vx4.z, vx4.w};
        float wx[4] = {wx4.x, wx4.y, wx4.z, wx4.w};

#pragma unroll
        for (int ii = 0; ii < 4; ii++) {
            u64 wxii = pack2(wx[ii], wx[ii]);
            u64 uxii = pack2(ux[ii], ux[ii]);
            u64 vxii = pack2(vx[ii], vx[ii]);
#pragma unroll
            for (int jp = 0; jp < 2; jp++) {
                u64 s2p = add2(wxii, wyp[jp]);
                u64 r   = rcp2_nr(s2p);
                u64 a   = mul2(d2Lp[ii][jp], r);
                float alo, ahi;
                unpack2(a, alo, ahi);
                u64 e   = pack2(fex2_fast(alo), fex2_fast(ahi));
                u64 cc  = fma2(uxii, uyp[jp], mul2(vxii, vyp[jp]));
                u64 re  = mul2(r, e);
                acc[ii][jp] = fma2(cc, re, acc[ii][jp]);
            }
        }
    }

    // Store 4x float4 rows, guarded
#pragma unroll
    for (int ii = 0; ii < 4; ii++) {
        int i = i0 + ib + ii;
        if (i >= N) continue;
        int j = j0 + jb;
        float a0, a1, a2, a3;
        unpack2(acc[ii][0], a0, a1);
        unpack2(acc[ii][1], a2, a3);
        if (j + 3 < M) {
            float4 v = make_float4(a0, a1, a2, a3);
            *(float4*)&out[(size_t)i * M + j] = v;
        } else {
            float av[4] = {a0, a1, a2, a3};
#pragma unroll
            for (int jj = 0; jj < 4; jj++)
                if (j + jj < M) out[(size_t)i * M + j + jj] = av[jj];
        }
    }
}

// ---------------------------------------------------------------------------
extern "C" void kernel_launch(void* const* d_in, const int* in_sizes, int n_in,
                              void* d_out, int out_size) {
    const float* x  = (const float*)d_in[0];
    const float* y  = (const float*)d_in[1];
    const float* W1 = (const float*)d_in[2];
    const float* b1 = (const float*)d_in[3];
    const float* Ww = (const float*)d_in[4];
    const float* bw = (const float*)d_in[5];
    const float* Wf = (const float*)d_in[6];
    const float* bf = (const float*)d_in[7];
    const float* Ws = (const float*)d_in[8];
    const float* bs = (const float*)d_in[9];
    float* out = (float*)d_out;

    int N = in_sizes[0] / 3;
    int M = in_sizes[1] / 3;

    int total = N + M;
    feat_kernel<<<(total + 31) / 32, 256>>>(x, y, W1, b1, Ww, bw, Wf, bf,
                                            Ws, bs, N, M);

    dim3 grid((M + 63) / 64, (N + 63) / 64);
    pair_kernel<<<grid, 256>>>(x, y, out, N, M);
}